// round 16
// baseline (speedup 1.0000x reference)
#include <cuda_runtime.h>
#include <cuda_bf16.h>
#include <cuda_fp16.h>
#include <cstdint>

// Problem constants (fixed by the reference)
#define B_   2
#define T_   2048
#define C_   1024
#define H_   16
#define HS_  64
#define C3_  3072
#define BT_  (B_*T_)          // 4096 rows

// q pre-scale: 1/sqrt(64) * log2(e)  -> softmax runs in exp2 domain
#define QSCALE 0.18033688011112042f

// ---------------------------------------------------------------------------
// Scratch (device globals — no runtime allocation allowed)
// ---------------------------------------------------------------------------
__device__ __half g_xh [(size_t)BT_ * C_];     // x fp16
__device__ __half g_w1h[(size_t)C3_ * C_];     // W_kqv^T [N,K] fp16
__device__ __half g_yh [(size_t)BT_ * C_];     // attn out fp16
__device__ __half g_w2h[(size_t)C_  * C_];     // W_proj^T [N,K] fp16

// per-head attention operands [B, H, T, 64] fp16
#define NHE ((size_t)B_ * H_ * T_ * 64)
__device__ __half g_qh[NHE];                   // q fp16, pre-scaled QSCALE
__device__ __half g_kh[NHE], g_vh[NHE];        // k, v fp16

// ---------------------------------------------------------------------------
// PTX helpers (no 'a'-gated instructions)
// ---------------------------------------------------------------------------
__device__ __forceinline__ uint32_t smem_u32(const void* p) {
    uint32_t a;
    asm("{ .reg .u64 t; cvta.to.shared.u64 t, %1; cvt.u32.u64 %0, t; }"
        : "=r"(a) : "l"(p));
    return a;
}

#define CP_ASYNC16(dst, src) \
    asm volatile("cp.async.cg.shared.global [%0], [%1], 16;" \
                 :: "r"(dst), "l"(src) : "memory")
#define CP_COMMIT() asm volatile("cp.async.commit_group;" ::: "memory")
#define CP_WAIT1()  asm volatile("cp.async.wait_group 1;" ::: "memory")
#define CP_WAIT2()  asm volatile("cp.async.wait_group 2;" ::: "memory")

#define LDSM_X4(r0, r1, r2, r3, addr) \
    asm volatile("ldmatrix.sync.aligned.m8n8.x4.shared.b16 {%0,%1,%2,%3}, [%4];" \
                 : "=r"(r0), "=r"(r1), "=r"(r2), "=r"(r3) : "r"(addr))
#define LDSM_X4T(r0, r1, r2, r3, addr) \
    asm volatile("ldmatrix.sync.aligned.m8n8.x4.trans.shared.b16 {%0,%1,%2,%3}, [%4];" \
                 : "=r"(r0), "=r"(r1), "=r"(r2), "=r"(r3) : "r"(addr))

#define MMAH(c, a, b0, b1) \
    asm volatile("mma.sync.aligned.m16n8k16.row.col.f32.f16.f16.f32 " \
                 "{%0,%1,%2,%3}, {%4,%5,%6,%7}, {%8,%9}, {%0,%1,%2,%3};" \
                 : "+f"((c)[0]), "+f"((c)[1]), "+f"((c)[2]), "+f"((c)[3]) \
                 : "r"((a)[0]), "r"((a)[1]), "r"((a)[2]), "r"((a)[3]), \
                   "r"(b0), "r"(b1))

__device__ __forceinline__ uint32_t pack2(float a, float b) {
    __half2 t = __floats2half2_rn(a, b);
    return *reinterpret_cast<uint32_t*>(&t);
}

// ---------------------------------------------------------------------------
// Merged prep: blocks [0, 4096) convert x fp32->fp16; blocks [4096, 8192)
// transpose+convert the two weight matrices (96x32 tiles W_kqv, 32x32 W_proj).
// All blocks 256 threads.
// ---------------------------------------------------------------------------
__global__ __launch_bounds__(256)
void prep_all(const float* __restrict__ x, __half* __restrict__ xh,
              const float* __restrict__ W1, __half* __restrict__ O1,
              const float* __restrict__ W2, __half* __restrict__ O2)
{
    const int bx = blockIdx.x;
    if (bx < 4096) {
        // x convert: 1M float4 groups
        int i = bx * 256 + threadIdx.x;
        float4 v = reinterpret_cast<const float4*>(x)[i];
        reinterpret_cast<uint2*>(xh)[i] =
            make_uint2(pack2(v.x, v.y), pack2(v.z, v.w));
    } else {
        __shared__ float t[32][33];
        const int bxx = bx - 4096;            // 0..4095 = 128 ncol-tiles x 32 k-tiles
        const int nt = bxx & 127, kt = bxx >> 7;
        const bool second = nt >= 96;
        const float* W  = second ? W2 : W1;
        __half* out     = second ? O2 : O1;
        const int N     = second ? C_ : C3_;
        const int K     = C_;
        const int n0 = (second ? (nt - 96) : nt) * 32;
        const int k0 = kt * 32;
        const int tx = threadIdx.x & 31, ty = threadIdx.x >> 5;
        #pragma unroll
        for (int r = 0; r < 4; r++)
            t[ty + 8 * r][tx] = W[(size_t)(k0 + ty + 8 * r) * N + n0 + tx];
        __syncthreads();
        #pragma unroll
        for (int r = 0; r < 4; r++) {
            const int n = n0 + ty + 8 * r, k = k0 + tx;
            out[(size_t)n * K + k] = __float2half(t[tx][ty + 8 * r]);
        }
    }
}

// ---------------------------------------------------------------------------
// fp16 GEMM: C = A @ B^T. CTA tile 256x128, warp tile 64x64, occ 1,
// 4-stage cp.async pipeline, prefetch issued at TOP of iteration.
// EPI 1: QKV per-head split epilogue. EPI 2: bias + fp32 store.
// ---------------------------------------------------------------------------
#define GBM 256
#define GBN 128
#define GBK 64
#define STG_S 49152                   // A 32K + B 16K
#define NSTG 4
#define SMEM_TOTAL (NSTG * STG_S)     // 192KB, 1 CTA/SM

template<int ROWS>
__device__ __forceinline__ void load_tile_async(
    uint32_t s_base, const uint16_t* __restrict__ g,
    int ld, int row0, int k0, int tid)
{
    #pragma unroll
    for (int it = 0; it < ROWS / 32; it++) {
        int i = tid + it * 256;
        int row = i >> 3, c = i & 7;
        uint32_t dst = s_base + row * 128 + (((c ^ (row & 7))) << 4);
        const uint16_t* src = g + (size_t)(row0 + row) * ld + k0 + c * 8;
        CP_ASYNC16(dst, src);
    }
}

template<int EPI>
__global__ __launch_bounds__(256, 1)
void gemm_mma(const uint16_t* __restrict__ A,
              const uint16_t* __restrict__ Bt,
              const float* __restrict__ bias, float* __restrict__ C,
              __half* __restrict__ qh, __half* __restrict__ kh,
              __half* __restrict__ vh,
              int M, int N, int K)
{
    extern __shared__ char sm[];
    const uint32_t sbase = smem_u32(sm);
    const int tid = threadIdx.x;
    const int wid = tid >> 5, lane = tid & 31;
    const int wm = wid >> 1, wn = wid & 1;        // 4 x 2 warp grid
    const int m0 = blockIdx.y * GBM, n0 = blockIdx.x * GBN;

    float acc[4][8][4];                            // 64x64 warp tile
    #pragma unroll
    for (int mt = 0; mt < 4; mt++)
        #pragma unroll
        for (int nt = 0; nt < 8; nt++)
            #pragma unroll
            for (int j = 0; j < 4; j++) acc[mt][nt][j] = 0.f;

    const int nchunks = K / GBK;    // 16

    // Prologue: stages 0,1,2
    #pragma unroll
    for (int s = 0; s < 3; s++) {
        const uint32_t st = sbase + s * STG_S;
        load_tile_async<GBM>(st,         A,  K, m0, s * GBK, tid);
        load_tile_async<GBN>(st + 32768, Bt, K, n0, s * GBK, tid);
        CP_COMMIT();
    }

    const int a_row  = wm * 64 + (lane & 15);
    const int a_cadd = (lane >> 4);
    const int b_row  = wn * 64 + (lane & 7) + ((lane >> 4) << 3);
    const int b_cadd = (lane >> 3) & 1;

    for (int ch = 0; ch < nchunks; ch++) {
        CP_WAIT2();
        __syncthreads();

        // Early prefetch: buffer (ch+3)%4 == (ch-1)%4; all warps finished
        // iteration ch-1 at the barrier above -> safe to overwrite now.
        if (ch + 3 < nchunks) {
            const uint32_t nb = sbase + ((ch + 3) % NSTG) * STG_S;
            load_tile_async<GBM>(nb,         A,  K, m0, (ch + 3) * GBK, tid);
            load_tile_async<GBN>(nb + 32768, Bt, K, n0, (ch + 3) * GBK, tid);
        }
        CP_COMMIT();

        const uint32_t st = sbase + (ch % NSTG) * STG_S;
        const uint32_t sA = st, sB = st + 32768;

        #pragma unroll
        for (int ks = 0; ks < 4; ks++) {
            const int c16 = ks * 2;
            uint32_t a[4][4];
            #pragma unroll
            for (int mt = 0; mt < 4; mt++) {
                const int row = a_row + mt * 16;
                const int cc  = c16 + a_cadd;
                const uint32_t ad = sA + row * 128 + ((cc ^ (row & 7)) << 4);
                LDSM_X4(a[mt][0], a[mt][1], a[mt][2], a[mt][3], ad);
            }
            uint32_t b[4][4];
            #pragma unroll
            for (int ntp = 0; ntp < 4; ntp++) {
                const int row = b_row + ntp * 16;
                const int cc  = c16 + b_cadd;
                const uint32_t ad = sB + row * 128 + ((cc ^ (row & 7)) << 4);
                LDSM_X4(b[ntp][0], b[ntp][1], b[ntp][2], b[ntp][3], ad);
            }
            #pragma unroll
            for (int mt = 0; mt < 4; mt++)
                #pragma unroll
                for (int nt = 0; nt < 8; nt++)
                    MMAH(acc[mt][nt], a[mt],
                         b[nt >> 1][(nt & 1) * 2],
                         b[nt >> 1][(nt & 1) * 2 + 1]);
        }
    }

    const int gid = lane >> 2, tig = lane & 3;

    if (EPI == 2) {
        #pragma unroll
        for (int mt = 0; mt < 4; mt++) {
            #pragma unroll
            for (int nt = 0; nt < 8; nt++) {
                const int col = n0 + wn * 64 + nt * 8 + tig * 2;
                const float bx = bias[col], by = bias[col + 1];
                const int r0 = m0 + wm * 64 + mt * 16 + gid;
                float2 v0 = { acc[mt][nt][0] + bx, acc[mt][nt][1] + by };
                float2 v1 = { acc[mt][nt][2] + bx, acc[mt][nt][3] + by };
                *reinterpret_cast<float2*>(&C[(size_t)r0 * N + col])       = v0;
                *reinterpret_cast<float2*>(&C[(size_t)(r0 + 8) * N + col]) = v1;
            }
        }
    } else {  // EPI == 1: QKV per-head split epilogue (single fp16)
        #pragma unroll
        for (int mt = 0; mt < 4; mt++) {
            #pragma unroll
            for (int nt = 0; nt < 8; nt++) {
                const int col   = n0 + wn * 64 + nt * 8 + tig * 2;
                const int which = col >> 10;            // 0=q 1=k 2=v
                const int hh    = (col >> 6) & 15;
                const int d     = col & 63;
                const float sc  = (which == 0) ? QSCALE : 1.0f;
                __half* p = (which == 0) ? qh : (which == 1) ? kh : vh;
                #pragma unroll
                for (int rr = 0; rr < 2; rr++) {
                    const int r  = m0 + wm * 64 + mt * 16 + gid + rr * 8;
                    const int bb = r >> 11, t = r & 2047;
                    const size_t off = (((size_t)(bb * 16 + hh)) * 2048 + t) * 64 + d;
                    *reinterpret_cast<uint32_t*>(p + off) =
                        pack2(acc[mt][nt][rr * 2 + 0] * sc,
                              acc[mt][nt][rr * 2 + 1] * sc);
                }
            }
        }
    }
}

// ---------------------------------------------------------------------------
// MMA flash attention, single-pass fp16, 3-stage cp.async K/V pipeline,
// prefetch issued at TOP of iteration; exp2 softmax + rescale skip. occ 2.
// smem: Q 16K | 3 x (Kh 8K, Vh 8K) = 64KB
// ---------------------------------------------------------------------------
#define ATT_SMEM (16384 + 3 * 16384)

__device__ __forceinline__ void kv_load(uint32_t sb,
    const __half* __restrict__ kh, const __half* __restrict__ vh,
    size_t hb, int kt, int tid)
{
    const uint32_t stage = sb + 16384 + (kt % 3) * 16384;
    #pragma unroll
    for (int it = 0; it < 4; it++) {
        int i = tid + (it & 1) * 256;            // 0..511
        int row = i >> 3, c = i & 7;
        const __half* g = (it < 2) ? kh : vh;
        uint32_t dst = stage + ((it < 2) ? 0 : 8192)
                     + row * 128 + ((c ^ (row & 7)) << 4);
        CP_ASYNC16(dst, g + hb + (size_t)(kt * 64 + row) * 64 + c * 8);
    }
}

__global__ __launch_bounds__(256, 2)
void attn_mma(const __half* __restrict__ qh,
              const __half* __restrict__ kh, const __half* __restrict__ vh,
              __half* __restrict__ yh)
{
    extern __shared__ char sm[];
    const uint32_t sb = smem_u32(sm);
    const uint32_t sQ = sb;

    const int tid = threadIdx.x, wid = tid >> 5, lane = tid & 31;
    const int qt = gridDim.x - 1 - blockIdx.x;    // heavy q-tiles first
    const int h = blockIdx.y, b = blockIdx.z;
    const size_t hb = ((size_t)(b * H_ + h)) * T_ * 64;
    const int ktmax = 2 * (qt + 1);               // >= 2

    // Stage Q tile (128 rows x 8 x 16B)
    #pragma unroll
    for (int it = 0; it < 4; it++) {
        int i = tid + it * 256;
        int row = i >> 3, c = i & 7;
        uint32_t dst = sQ + row * 128 + ((c ^ (row & 7)) << 4);
        CP_ASYNC16(dst, qh + hb + (size_t)(qt * 128 + row) * 64 + c * 8);
    }
    CP_COMMIT();                                   // g0: Q
    kv_load(sb, kh, vh, hb, 0, tid);
    CP_COMMIT();                                   // g1: KV0
    kv_load(sb, kh, vh, hb, 1, tid);
    CP_COMMIT();                                   // g2: KV1

    const int gid = lane >> 2, tig = lane & 3;
    const int arow   = wid * 16 + (lane & 15);
    const int acadd  = lane >> 4;
    const int kbrow  = (lane & 7) + ((lane >> 4) << 3);
    const int kbcadd = (lane >> 3) & 1;
    const int vbrow  = (lane & 7) + (((lane >> 3) & 1) << 3);
    const int vbcadd = lane >> 4;

    // Q fragments (loop-invariant), hoisted after g0 lands
    CP_WAIT2();
    __syncthreads();
    uint32_t aq[4][4];
    #pragma unroll
    for (int ks = 0; ks < 4; ks++) {
        const int c16 = ks * 2 + acadd;
        uint32_t ad = sQ + arow * 128 + ((c16 ^ (arow & 7)) << 4);
        LDSM_X4(aq[ks][0], aq[ks][1], aq[ks][2], aq[ks][3], ad);
    }

    float m0 = -1e30f, m1 = -1e30f, l0 = 0.f, l1 = 0.f;
    float O[8][4];
    #pragma unroll
    for (int d = 0; d < 8; d++)
        #pragma unroll
        for (int j = 0; j < 4; j++) O[d][j] = 0.f;

    const int rg0 = qt * 128 + wid * 16 + gid;

    for (int kt = 0; kt < ktmax; kt++) {
        CP_WAIT1();
        __syncthreads();

        // Early prefetch: buffer (kt+2)%3 == (kt-1)%3; all warps finished
        // iteration kt-1 at the barrier above -> safe to overwrite now.
        if (kt + 2 < ktmax)
            kv_load(sb, kh, vh, hb, kt + 2, tid);
        CP_COMMIT();

        const uint32_t stage = sb + 16384 + (kt % 3) * 16384;
        const uint32_t sKh = stage, sVh = stage + 8192;

        const bool active = (kt * 64) <= (qt * 128 + wid * 16 + 15);
        if (active) {
            // ---- S = QK^T (exp2 domain) ----
            float S[8][4];
            #pragma unroll
            for (int nt = 0; nt < 8; nt++)
                #pragma unroll
                for (int j = 0; j < 4; j++) S[nt][j] = 0.f;

            #pragma unroll
            for (int ks = 0; ks < 4; ks++) {
                const int c16 = ks * 2;
                uint32_t bh[4][4];
                #pragma unroll
                for (int jn = 0; jn < 4; jn++) {
                    const int row = jn * 16 + kbrow;
                    const int cc  = c16 + kbcadd;
                    uint32_t ad = sKh + row * 128 + ((cc ^ (row & 7)) << 4);
                    LDSM_X4(bh[jn][0], bh[jn][1], bh[jn][2], bh[jn][3], ad);
                }
                #pragma unroll
                for (int nt = 0; nt < 8; nt++)
                    MMAH(S[nt], aq[ks],
                         bh[nt >> 1][(nt & 1) * 2],
                         bh[nt >> 1][(nt & 1) * 2 + 1]);
            }

            // ---- causal mask (diagonal tiles only) ----
            if (kt >= 2 * qt) {
                #pragma unroll
                for (int nt = 0; nt < 8; nt++) {
                    const int jg = kt * 64 + nt * 8 + tig * 2;
                    if (jg     > rg0)     S[nt][0] = -1e30f;
                    if (jg + 1 > rg0)     S[nt][1] = -1e30f;
                    if (jg     > rg0 + 8) S[nt][2] = -1e30f;
                    if (jg + 1 > rg0 + 8) S[nt][3] = -1e30f;
                }
            }

            // ---- online softmax (exp2), skip rescale when max unchanged ----
            float t0 = -1e30f, t1 = -1e30f;
            #pragma unroll
            for (int nt = 0; nt < 8; nt++) {
                t0 = fmaxf(t0, fmaxf(S[nt][0], S[nt][1]));
                t1 = fmaxf(t1, fmaxf(S[nt][2], S[nt][3]));
            }
            t0 = fmaxf(t0, __shfl_xor_sync(0xffffffffu, t0, 1));
            t0 = fmaxf(t0, __shfl_xor_sync(0xffffffffu, t0, 2));
            t1 = fmaxf(t1, __shfl_xor_sync(0xffffffffu, t1, 1));
            t1 = fmaxf(t1, __shfl_xor_sync(0xffffffffu, t1, 2));
            const float mn0 = fmaxf(m0, t0), mn1 = fmaxf(m1, t1);
            const bool upd = __any_sync(0xffffffffu, (mn0 > m0) | (mn1 > m1));
            if (upd) {
                const float a0 = exp2f(m0 - mn0), a1 = exp2f(m1 - mn1);
                l0 *= a0;  l1 *= a1;
                #pragma unroll
                for (int d = 0; d < 8; d++) {
                    O[d][0] *= a0; O[d][1] *= a0;
                    O[d][2] *= a1; O[d][3] *= a1;
                }
                m0 = mn0; m1 = mn1;
            }

            // ---- P = exp2(S-m), packed-convert fp16 A-fragments ----
            uint32_t pf[4][4];
            #pragma unroll
            for (int nt = 0; nt < 8; nt++) {
                const float p0 = exp2f(S[nt][0] - m0);
                const float p1 = exp2f(S[nt][1] - m0);
                const float p2 = exp2f(S[nt][2] - m1);
                const float p3 = exp2f(S[nt][3] - m1);
                l0 += p0 + p1;
                l1 += p2 + p3;
                const int jb = nt >> 1, o = (nt & 1) * 2;
                pf[jb][o]     = pack2(p0, p1);
                pf[jb][o + 1] = pack2(p2, p3);
            }

            // ---- O += P @ V (single pass) ----
            #pragma unroll
            for (int jb = 0; jb < 4; jb++) {
                #pragma unroll
                for (int dp = 0; dp < 4; dp++) {
                    const int row = jb * 16 + vbrow;
                    const int cc  = dp * 2 + vbcadd;
                    uint32_t vv[4];
                    uint32_t ad = sVh + row * 128 + ((cc ^ (row & 7)) << 4);
                    LDSM_X4T(vv[0], vv[1], vv[2], vv[3], ad);
                    const int d0 = dp * 2;
                    MMAH(O[d0],     pf[jb], vv[0], vv[1]);
                    MMAH(O[d0 + 1], pf[jb], vv[2], vv[3]);
                }
            }
        }
    }

    // ---- epilogue: normalize + write fp16 ----
    l0 += __shfl_xor_sync(0xffffffffu, l0, 1);
    l0 += __shfl_xor_sync(0xffffffffu, l0, 2);
    l1 += __shfl_xor_sync(0xffffffffu, l1, 1);
    l1 += __shfl_xor_sync(0xffffffffu, l1, 2);
    const float inv0 = 1.f / l0, inv1 = 1.f / l1;

    const size_t row0 = (size_t)(b * T_ + rg0) * C_;
    const size_t row1 = row0 + (size_t)8 * C_;
    #pragma unroll
    for (int d = 0; d < 8; d++) {
        const int c = h * 64 + d * 8 + tig * 2;
        *reinterpret_cast<uint32_t*>(yh + row0 + c) =
            pack2(O[d][0] * inv0, O[d][1] * inv0);
        *reinterpret_cast<uint32_t*>(yh + row1 + c) =
            pack2(O[d][2] * inv1, O[d][3] * inv1);
    }
}

// ---------------------------------------------------------------------------
extern "C" void kernel_launch(void* const* d_in, const int* in_sizes, int n_in,
                              void* d_out, int out_size)
{
    const float* x     = (const float*)d_in[0];
    const float* wkqv  = (const float*)d_in[1];
    const float* wproj = (const float*)d_in[2];
    const float* bproj = (const float*)d_in[3];
    float* out = (float*)d_out;

    __half *xh, *w1h, *yh, *w2h, *qh, *kh, *vh;
    cudaGetSymbolAddress((void**)&xh,  g_xh);
    cudaGetSymbolAddress((void**)&w1h, g_w1h);
    cudaGetSymbolAddress((void**)&yh,  g_yh);
    cudaGetSymbolAddress((void**)&w2h, g_w2h);
    cudaGetSymbolAddress((void**)&qh,  g_qh);
    cudaGetSymbolAddress((void**)&kh,  g_kh);
    cudaGetSymbolAddress((void**)&vh,  g_vh);

    cudaFuncSetAttribute((const void*)gemm_mma<1>,
                         cudaFuncAttributeMaxDynamicSharedMemorySize, SMEM_TOTAL);
    cudaFuncSetAttribute((const void*)gemm_mma<2>,
                         cudaFuncAttributeMaxDynamicSharedMemorySize, SMEM_TOTAL);
    cudaFuncSetAttribute((const void*)attn_mma,
                         cudaFuncAttributeMaxDynamicSharedMemorySize, ATT_SMEM);

    // Prep (merged: x convert + both weight transposes, one launch)
    prep_all<<<8192, 256>>>(x, xh, wkqv, w1h, wproj, w2h);

    // 1) QKV GEMM (single-pass fp16, 256x128 tile, 4-stage, early prefetch)
    {
        dim3 grid(C3_ / GBN, BT_ / GBM);   // (24, 16)
        gemm_mma<1><<<grid, 256, SMEM_TOTAL>>>(
            (const uint16_t*)xh, (const uint16_t*)w1h,
            nullptr, nullptr, qh, kh, vh, BT_, C3_, C_);
    }

    // 2) MMA flash attention (exp2 softmax + rescale skip, occ 2) -> yh
    {
        dim3 grid(T_ / 128, H_, B_);       // (16, 16, 2)
        attn_mma<<<grid, 256, ATT_SMEM>>>(qh, kh, vh, yh);
    }

    // 3) proj GEMM (single-pass fp16, 256x128 tile, 4-stage) + bias -> out
    {
        dim3 grid(C_ / GBN, BT_ / GBM);    // (8, 16)
        gemm_mma<2><<<grid, 256, SMEM_TOTAL>>>(
            (const uint16_t*)yh, (const uint16_t*)w2h,
            bproj, out, nullptr, nullptr, nullptr, BT_, C_, C_);
    }
}

// round 17
// speedup vs baseline: 1.0519x; 1.0519x over previous
#include <cuda_runtime.h>
#include <cuda_bf16.h>
#include <cuda_fp16.h>
#include <cstdint>

// Problem constants (fixed by the reference)
#define B_   2
#define T_   2048
#define C_   1024
#define H_   16
#define HS_  64
#define C3_  3072
#define BT_  (B_*T_)          // 4096 rows

// q pre-scale: 1/sqrt(64) * log2(e)  -> softmax runs in exp2 domain
#define QSCALE 0.18033688011112042f

// ---------------------------------------------------------------------------
// Scratch (device globals — no runtime allocation allowed)
// ---------------------------------------------------------------------------
__device__ __half g_xh [(size_t)BT_ * C_];     // x fp16
__device__ __half g_w1h[(size_t)C3_ * C_];     // W_kqv^T [N,K] fp16
__device__ __half g_yh [(size_t)BT_ * C_];     // attn out fp16
__device__ __half g_w2h[(size_t)C_  * C_];     // W_proj^T [N,K] fp16

// per-head attention operands [B, H, T, 64] fp16
#define NHE ((size_t)B_ * H_ * T_ * 64)
__device__ __half g_qh[NHE];                   // q fp16, pre-scaled QSCALE
__device__ __half g_kh[NHE], g_vh[NHE];        // k, v fp16

// ---------------------------------------------------------------------------
// PTX helpers (no 'a'-gated instructions)
// ---------------------------------------------------------------------------
__device__ __forceinline__ uint32_t smem_u32(const void* p) {
    uint32_t a;
    asm("{ .reg .u64 t; cvta.to.shared.u64 t, %1; cvt.u32.u64 %0, t; }"
        : "=r"(a) : "l"(p));
    return a;
}

#define CP_ASYNC16(dst, src) \
    asm volatile("cp.async.cg.shared.global [%0], [%1], 16;" \
                 :: "r"(dst), "l"(src) : "memory")
#define CP_COMMIT() asm volatile("cp.async.commit_group;" ::: "memory")
#define CP_WAIT1()  asm volatile("cp.async.wait_group 1;" ::: "memory")
#define CP_WAIT2()  asm volatile("cp.async.wait_group 2;" ::: "memory")

#define LDSM_X4(r0, r1, r2, r3, addr) \
    asm volatile("ldmatrix.sync.aligned.m8n8.x4.shared.b16 {%0,%1,%2,%3}, [%4];" \
                 : "=r"(r0), "=r"(r1), "=r"(r2), "=r"(r3) : "r"(addr))
#define LDSM_X4T(r0, r1, r2, r3, addr) \
    asm volatile("ldmatrix.sync.aligned.m8n8.x4.trans.shared.b16 {%0,%1,%2,%3}, [%4];" \
                 : "=r"(r0), "=r"(r1), "=r"(r2), "=r"(r3) : "r"(addr))

#define MMAH(c, a, b0, b1) \
    asm volatile("mma.sync.aligned.m16n8k16.row.col.f32.f16.f16.f32 " \
                 "{%0,%1,%2,%3}, {%4,%5,%6,%7}, {%8,%9}, {%0,%1,%2,%3};" \
                 : "+f"((c)[0]), "+f"((c)[1]), "+f"((c)[2]), "+f"((c)[3]) \
                 : "r"((a)[0]), "r"((a)[1]), "r"((a)[2]), "r"((a)[3]), \
                   "r"(b0), "r"(b1))

__device__ __forceinline__ uint32_t pack2(float a, float b) {
    __half2 t = __floats2half2_rn(a, b);
    return *reinterpret_cast<uint32_t*>(&t);
}

// ---------------------------------------------------------------------------
// Merged prep: blocks [0, 4096) convert x fp32->fp16; blocks [4096, 8192)
// transpose+convert the two weight matrices.
// ---------------------------------------------------------------------------
__global__ __launch_bounds__(256)
void prep_all(const float* __restrict__ x, __half* __restrict__ xh,
              const float* __restrict__ W1, __half* __restrict__ O1,
              const float* __restrict__ W2, __half* __restrict__ O2)
{
    const int bx = blockIdx.x;
    if (bx < 4096) {
        int i = bx * 256 + threadIdx.x;
        float4 v = reinterpret_cast<const float4*>(x)[i];
        reinterpret_cast<uint2*>(xh)[i] =
            make_uint2(pack2(v.x, v.y), pack2(v.z, v.w));
    } else {
        __shared__ float t[32][33];
        const int bxx = bx - 4096;            // 0..4095 = 128 ncol-tiles x 32 k-tiles
        const int nt = bxx & 127, kt = bxx >> 7;
        const bool second = nt >= 96;
        const float* W  = second ? W2 : W1;
        __half* out     = second ? O2 : O1;
        const int N     = second ? C_ : C3_;
        const int K     = C_;
        const int n0 = (second ? (nt - 96) : nt) * 32;
        const int k0 = kt * 32;
        const int tx = threadIdx.x & 31, ty = threadIdx.x >> 5;
        #pragma unroll
        for (int r = 0; r < 4; r++)
            t[ty + 8 * r][tx] = W[(size_t)(k0 + ty + 8 * r) * N + n0 + tx];
        __syncthreads();
        #pragma unroll
        for (int r = 0; r < 4; r++) {
            const int n = n0 + ty + 8 * r, k = k0 + tx;
            out[(size_t)n * K + k] = __float2half(t[tx][ty + 8 * r]);
        }
    }
}

// ---------------------------------------------------------------------------
// fp16 GEMM: C = A @ B^T. CTA tile 256x128, warp tile 64x64, occ 1,
// 4-stage cp.async pipeline, prefetch at BOTTOM of iteration (R15 order —
// the R16 top-of-loop prefetch delayed the critical path at low occupancy).
// EPI 1: QKV per-head split epilogue. EPI 2: bias + fp32 store.
// ---------------------------------------------------------------------------
#define GBM 256
#define GBN 128
#define GBK 64
#define STG_S 49152                   // A 32K + B 16K
#define NSTG 4
#define SMEM_TOTAL (NSTG * STG_S)     // 192KB, 1 CTA/SM

template<int ROWS>
__device__ __forceinline__ void load_tile_async(
    uint32_t s_base, const uint16_t* __restrict__ g,
    int ld, int row0, int k0, int tid)
{
    #pragma unroll
    for (int it = 0; it < ROWS / 32; it++) {
        int i = tid + it * 256;
        int row = i >> 3, c = i & 7;
        uint32_t dst = s_base + row * 128 + (((c ^ (row & 7))) << 4);
        const uint16_t* src = g + (size_t)(row0 + row) * ld + k0 + c * 8;
        CP_ASYNC16(dst, src);
    }
}

template<int EPI>
__global__ __launch_bounds__(256, 1)
void gemm_mma(const uint16_t* __restrict__ A,
              const uint16_t* __restrict__ Bt,
              const float* __restrict__ bias, float* __restrict__ C,
              __half* __restrict__ qh, __half* __restrict__ kh,
              __half* __restrict__ vh,
              int M, int N, int K)
{
    extern __shared__ char sm[];
    const uint32_t sbase = smem_u32(sm);
    const int tid = threadIdx.x;
    const int wid = tid >> 5, lane = tid & 31;
    const int wm = wid >> 1, wn = wid & 1;        // 4 x 2 warp grid
    const int m0 = blockIdx.y * GBM, n0 = blockIdx.x * GBN;

    float acc[4][8][4];                            // 64x64 warp tile
    #pragma unroll
    for (int mt = 0; mt < 4; mt++)
        #pragma unroll
        for (int nt = 0; nt < 8; nt++)
            #pragma unroll
            for (int j = 0; j < 4; j++) acc[mt][nt][j] = 0.f;

    const int nchunks = K / GBK;    // 16

    // Prologue: stages 0,1,2
    #pragma unroll
    for (int s = 0; s < 3; s++) {
        const uint32_t st = sbase + s * STG_S;
        load_tile_async<GBM>(st,         A,  K, m0, s * GBK, tid);
        load_tile_async<GBN>(st + 32768, Bt, K, n0, s * GBK, tid);
        CP_COMMIT();
    }

    const int a_row  = wm * 64 + (lane & 15);
    const int a_cadd = (lane >> 4);
    const int b_row  = wn * 64 + (lane & 7) + ((lane >> 4) << 3);
    const int b_cadd = (lane >> 3) & 1;

    for (int ch = 0; ch < nchunks; ch++) {
        CP_WAIT2();
        __syncthreads();

        const uint32_t st = sbase + (ch % NSTG) * STG_S;
        const uint32_t sA = st, sB = st + 32768;

        #pragma unroll
        for (int ks = 0; ks < 4; ks++) {
            const int c16 = ks * 2;
            uint32_t a[4][4];
            #pragma unroll
            for (int mt = 0; mt < 4; mt++) {
                const int row = a_row + mt * 16;
                const int cc  = c16 + a_cadd;
                const uint32_t ad = sA + row * 128 + ((cc ^ (row & 7)) << 4);
                LDSM_X4(a[mt][0], a[mt][1], a[mt][2], a[mt][3], ad);
            }
            uint32_t b[4][4];
            #pragma unroll
            for (int ntp = 0; ntp < 4; ntp++) {
                const int row = b_row + ntp * 16;
                const int cc  = c16 + b_cadd;
                const uint32_t ad = sB + row * 128 + ((cc ^ (row & 7)) << 4);
                LDSM_X4(b[ntp][0], b[ntp][1], b[ntp][2], b[ntp][3], ad);
            }
            #pragma unroll
            for (int mt = 0; mt < 4; mt++)
                #pragma unroll
                for (int nt = 0; nt < 8; nt++)
                    MMAH(acc[mt][nt], a[mt],
                         b[nt >> 1][(nt & 1) * 2],
                         b[nt >> 1][(nt & 1) * 2 + 1]);
        }

        if (ch + 3 < nchunks) {
            const uint32_t nb = sbase + ((ch + 3) % NSTG) * STG_S;
            load_tile_async<GBM>(nb,         A,  K, m0, (ch + 3) * GBK, tid);
            load_tile_async<GBN>(nb + 32768, Bt, K, n0, (ch + 3) * GBK, tid);
        }
        CP_COMMIT();
    }

    const int gid = lane >> 2, tig = lane & 3;

    if (EPI == 2) {
        #pragma unroll
        for (int mt = 0; mt < 4; mt++) {
            #pragma unroll
            for (int nt = 0; nt < 8; nt++) {
                const int col = n0 + wn * 64 + nt * 8 + tig * 2;
                const float bx = bias[col], by = bias[col + 1];
                const int r0 = m0 + wm * 64 + mt * 16 + gid;
                float2 v0 = { acc[mt][nt][0] + bx, acc[mt][nt][1] + by };
                float2 v1 = { acc[mt][nt][2] + bx, acc[mt][nt][3] + by };
                *reinterpret_cast<float2*>(&C[(size_t)r0 * N + col])       = v0;
                *reinterpret_cast<float2*>(&C[(size_t)(r0 + 8) * N + col]) = v1;
            }
        }
    } else {  // EPI == 1: QKV per-head split epilogue (single fp16)
        #pragma unroll
        for (int mt = 0; mt < 4; mt++) {
            #pragma unroll
            for (int nt = 0; nt < 8; nt++) {
                const int col   = n0 + wn * 64 + nt * 8 + tig * 2;
                const int which = col >> 10;            // 0=q 1=k 2=v
                const int hh    = (col >> 6) & 15;
                const int d     = col & 63;
                const float sc  = (which == 0) ? QSCALE : 1.0f;
                __half* p = (which == 0) ? qh : (which == 1) ? kh : vh;
                #pragma unroll
                for (int rr = 0; rr < 2; rr++) {
                    const int r  = m0 + wm * 64 + mt * 16 + gid + rr * 8;
                    const int bb = r >> 11, t = r & 2047;
                    const size_t off = (((size_t)(bb * 16 + hh)) * 2048 + t) * 64 + d;
                    *reinterpret_cast<uint32_t*>(p + off) =
                        pack2(acc[mt][nt][rr * 2 + 0] * sc,
                              acc[mt][nt][rr * 2 + 1] * sc);
                }
            }
        }
    }
}

// ---------------------------------------------------------------------------
// MMA flash attention, single-pass fp16, 3-stage cp.async K/V pipeline,
// prefetch at BOTTOM of iteration (R15 order); exp2 softmax + rescale skip.
// occ 2. smem: Q 16K | 3 x (Kh 8K, Vh 8K) = 64KB
// ---------------------------------------------------------------------------
#define ATT_SMEM (16384 + 3 * 16384)

__device__ __forceinline__ void kv_load(uint32_t sb,
    const __half* __restrict__ kh, const __half* __restrict__ vh,
    size_t hb, int kt, int tid)
{
    const uint32_t stage = sb + 16384 + (kt % 3) * 16384;
    #pragma unroll
    for (int it = 0; it < 4; it++) {
        int i = tid + (it & 1) * 256;            // 0..511
        int row = i >> 3, c = i & 7;
        const __half* g = (it < 2) ? kh : vh;
        uint32_t dst = stage + ((it < 2) ? 0 : 8192)
                     + row * 128 + ((c ^ (row & 7)) << 4);
        CP_ASYNC16(dst, g + hb + (size_t)(kt * 64 + row) * 64 + c * 8);
    }
}

__global__ __launch_bounds__(256, 2)
void attn_mma(const __half* __restrict__ qh,
              const __half* __restrict__ kh, const __half* __restrict__ vh,
              __half* __restrict__ yh)
{
    extern __shared__ char sm[];
    const uint32_t sb = smem_u32(sm);
    const uint32_t sQ = sb;

    const int tid = threadIdx.x, wid = tid >> 5, lane = tid & 31;
    const int qt = gridDim.x - 1 - blockIdx.x;    // heavy q-tiles first
    const int h = blockIdx.y, b = blockIdx.z;
    const size_t hb = ((size_t)(b * H_ + h)) * T_ * 64;
    const int ktmax = 2 * (qt + 1);               // >= 2

    // Stage Q tile (128 rows x 8 x 16B)
    #pragma unroll
    for (int it = 0; it < 4; it++) {
        int i = tid + it * 256;
        int row = i >> 3, c = i & 7;
        uint32_t dst = sQ + row * 128 + ((c ^ (row & 7)) << 4);
        CP_ASYNC16(dst, qh + hb + (size_t)(qt * 128 + row) * 64 + c * 8);
    }
    CP_COMMIT();                                   // g0: Q
    kv_load(sb, kh, vh, hb, 0, tid);
    CP_COMMIT();                                   // g1: KV0
    kv_load(sb, kh, vh, hb, 1, tid);
    CP_COMMIT();                                   // g2: KV1

    const int gid = lane >> 2, tig = lane & 3;
    const int arow   = wid * 16 + (lane & 15);
    const int acadd  = lane >> 4;
    const int kbrow  = (lane & 7) + ((lane >> 4) << 3);
    const int kbcadd = (lane >> 3) & 1;
    const int vbrow  = (lane & 7) + (((lane >> 3) & 1) << 3);
    const int vbcadd = lane >> 4;

    // Q fragments (loop-invariant), hoisted after g0 lands
    CP_WAIT2();
    __syncthreads();
    uint32_t aq[4][4];
    #pragma unroll
    for (int ks = 0; ks < 4; ks++) {
        const int c16 = ks * 2 + acadd;
        uint32_t ad = sQ + arow * 128 + ((c16 ^ (arow & 7)) << 4);
        LDSM_X4(aq[ks][0], aq[ks][1], aq[ks][2], aq[ks][3], ad);
    }

    float m0 = -1e30f, m1 = -1e30f, l0 = 0.f, l1 = 0.f;
    float O[8][4];
    #pragma unroll
    for (int d = 0; d < 8; d++)
        #pragma unroll
        for (int j = 0; j < 4; j++) O[d][j] = 0.f;

    const int rg0 = qt * 128 + wid * 16 + gid;

    for (int kt = 0; kt < ktmax; kt++) {
        CP_WAIT1();
        __syncthreads();

        const uint32_t stage = sb + 16384 + (kt % 3) * 16384;
        const uint32_t sKh = stage, sVh = stage + 8192;

        const bool active = (kt * 64) <= (qt * 128 + wid * 16 + 15);
        if (active) {
            // ---- S = QK^T (exp2 domain) ----
            float S[8][4];
            #pragma unroll
            for (int nt = 0; nt < 8; nt++)
                #pragma unroll
                for (int j = 0; j < 4; j++) S[nt][j] = 0.f;

            #pragma unroll
            for (int ks = 0; ks < 4; ks++) {
                const int c16 = ks * 2;
                uint32_t bh[4][4];
                #pragma unroll
                for (int jn = 0; jn < 4; jn++) {
                    const int row = jn * 16 + kbrow;
                    const int cc  = c16 + kbcadd;
                    uint32_t ad = sKh + row * 128 + ((cc ^ (row & 7)) << 4);
                    LDSM_X4(bh[jn][0], bh[jn][1], bh[jn][2], bh[jn][3], ad);
                }
                #pragma unroll
                for (int nt = 0; nt < 8; nt++)
                    MMAH(S[nt], aq[ks],
                         bh[nt >> 1][(nt & 1) * 2],
                         bh[nt >> 1][(nt & 1) * 2 + 1]);
            }

            // ---- causal mask (diagonal tiles only) ----
            if (kt >= 2 * qt) {
                #pragma unroll
                for (int nt = 0; nt < 8; nt++) {
                    const int jg = kt * 64 + nt * 8 + tig * 2;
                    if (jg     > rg0)     S[nt][0] = -1e30f;
                    if (jg + 1 > rg0)     S[nt][1] = -1e30f;
                    if (jg     > rg0 + 8) S[nt][2] = -1e30f;
                    if (jg + 1 > rg0 + 8) S[nt][3] = -1e30f;
                }
            }

            // ---- online softmax (exp2), skip rescale when max unchanged ----
            float t0 = -1e30f, t1 = -1e30f;
            #pragma unroll
            for (int nt = 0; nt < 8; nt++) {
                t0 = fmaxf(t0, fmaxf(S[nt][0], S[nt][1]));
                t1 = fmaxf(t1, fmaxf(S[nt][2], S[nt][3]));
            }
            t0 = fmaxf(t0, __shfl_xor_sync(0xffffffffu, t0, 1));
            t0 = fmaxf(t0, __shfl_xor_sync(0xffffffffu, t0, 2));
            t1 = fmaxf(t1, __shfl_xor_sync(0xffffffffu, t1, 1));
            t1 = fmaxf(t1, __shfl_xor_sync(0xffffffffu, t1, 2));
            const float mn0 = fmaxf(m0, t0), mn1 = fmaxf(m1, t1);
            const bool upd = __any_sync(0xffffffffu, (mn0 > m0) | (mn1 > m1));
            if (upd) {
                const float a0 = exp2f(m0 - mn0), a1 = exp2f(m1 - mn1);
                l0 *= a0;  l1 *= a1;
                #pragma unroll
                for (int d = 0; d < 8; d++) {
                    O[d][0] *= a0; O[d][1] *= a0;
                    O[d][2] *= a1; O[d][3] *= a1;
                }
                m0 = mn0; m1 = mn1;
            }

            // ---- P = exp2(S-m), packed-convert fp16 A-fragments ----
            uint32_t pf[4][4];
            #pragma unroll
            for (int nt = 0; nt < 8; nt++) {
                const float p0 = exp2f(S[nt][0] - m0);
                const float p1 = exp2f(S[nt][1] - m0);
                const float p2 = exp2f(S[nt][2] - m1);
                const float p3 = exp2f(S[nt][3] - m1);
                l0 += p0 + p1;
                l1 += p2 + p3;
                const int jb = nt >> 1, o = (nt & 1) * 2;
                pf[jb][o]     = pack2(p0, p1);
                pf[jb][o + 1] = pack2(p2, p3);
            }

            // ---- O += P @ V (single pass) ----
            #pragma unroll
            for (int jb = 0; jb < 4; jb++) {
                #pragma unroll
                for (int dp = 0; dp < 4; dp++) {
                    const int row = jb * 16 + vbrow;
                    const int cc  = dp * 2 + vbcadd;
                    uint32_t vv[4];
                    uint32_t ad = sVh + row * 128 + ((cc ^ (row & 7)) << 4);
                    LDSM_X4T(vv[0], vv[1], vv[2], vv[3], ad);
                    const int d0 = dp * 2;
                    MMAH(O[d0],     pf[jb], vv[0], vv[1]);
                    MMAH(O[d0 + 1], pf[jb], vv[2], vv[3]);
                }
            }
        }

        if (kt + 2 < ktmax)
            kv_load(sb, kh, vh, hb, kt + 2, tid);
        CP_COMMIT();
    }

    // ---- epilogue: normalize + write fp16 ----
    l0 += __shfl_xor_sync(0xffffffffu, l0, 1);
    l0 += __shfl_xor_sync(0xffffffffu, l0, 2);
    l1 += __shfl_xor_sync(0xffffffffu, l1, 1);
    l1 += __shfl_xor_sync(0xffffffffu, l1, 2);
    const float inv0 = 1.f / l0, inv1 = 1.f / l1;

    const size_t row0 = (size_t)(b * T_ + rg0) * C_;
    const size_t row1 = row0 + (size_t)8 * C_;
    #pragma unroll
    for (int d = 0; d < 8; d++) {
        const int c = h * 64 + d * 8 + tig * 2;
        *reinterpret_cast<uint32_t*>(yh + row0 + c) =
            pack2(O[d][0] * inv0, O[d][1] * inv0);
        *reinterpret_cast<uint32_t*>(yh + row1 + c) =
            pack2(O[d][2] * inv1, O[d][3] * inv1);
    }
}

// ---------------------------------------------------------------------------
extern "C" void kernel_launch(void* const* d_in, const int* in_sizes, int n_in,
                              void* d_out, int out_size)
{
    const float* x     = (const float*)d_in[0];
    const float* wkqv  = (const float*)d_in[1];
    const float* wproj = (const float*)d_in[2];
    const float* bproj = (const float*)d_in[3];
    float* out = (float*)d_out;

    __half *xh, *w1h, *yh, *w2h, *qh, *kh, *vh;
    cudaGetSymbolAddress((void**)&xh,  g_xh);
    cudaGetSymbolAddress((void**)&w1h, g_w1h);
    cudaGetSymbolAddress((void**)&yh,  g_yh);
    cudaGetSymbolAddress((void**)&w2h, g_w2h);
    cudaGetSymbolAddress((void**)&qh,  g_qh);
    cudaGetSymbolAddress((void**)&kh,  g_kh);
    cudaGetSymbolAddress((void**)&vh,  g_vh);

    cudaFuncSetAttribute((const void*)gemm_mma<1>,
                         cudaFuncAttributeMaxDynamicSharedMemorySize, SMEM_TOTAL);
    cudaFuncSetAttribute((const void*)gemm_mma<2>,
                         cudaFuncAttributeMaxDynamicSharedMemorySize, SMEM_TOTAL);
    cudaFuncSetAttribute((const void*)attn_mma,
                         cudaFuncAttributeMaxDynamicSharedMemorySize, ATT_SMEM);

    // Prep (merged: x convert + both weight transposes, one launch)
    prep_all<<<8192, 256>>>(x, xh, wkqv, w1h, wproj, w2h);

    // 1) QKV GEMM (single-pass fp16, 256x128 tile, 4-stage)
    {
        dim3 grid(C3_ / GBN, BT_ / GBM);   // (24, 16)
        gemm_mma<1><<<grid, 256, SMEM_TOTAL>>>(
            (const uint16_t*)xh, (const uint16_t*)w1h,
            nullptr, nullptr, qh, kh, vh, BT_, C3_, C_);
    }

    // 2) MMA flash attention (exp2 softmax + rescale skip, occ 2) -> yh
    {
        dim3 grid(T_ / 128, H_, B_);       // (16, 16, 2)
        attn_mma<<<grid, 256, ATT_SMEM>>>(qh, kh, vh, yh);
    }

    // 3) proj GEMM (single-pass fp16, 256x128 tile, 4-stage) + bias -> out
    {
        dim3 grid(C_ / GBN, BT_ / GBM);    // (8, 16)
        gemm_mma<2><<<grid, 256, SMEM_TOTAL>>>(
            (const uint16_t*)yh, (const uint16_t*)w2h,
            bproj, out, nullptr, nullptr, nullptr, BT_, C_, C_);
    }
}